// round 15
// baseline (speedup 1.0000x reference)
#include <cuda_runtime.h>
#include <cstdint>

// CapsNet dynamic routing. b_t = u * Vsum so u (189 MB) is never materialized.
// Pass 0 (uniform c) is algebraically a GEMM: s0[b,od] = 0.1 * sum_{ik} x[b,ik]
// * W[ik,od] -> dedicated split-K register-tiled GEMM (20 independent fma2
// chains/thread). Passes 1,2 use the proven route kernel (f32x2, Taylor exp)
// with Vsum staged in smem to free registers for o-chain ILP.

namespace {
constexpr int B_  = 256;
constexpr int IC_ = 1152;
constexpr int ID_ = 8;
constexpr int OC_ = 10;
constexpr int OD_ = 16;
constexpr int SOD = B_ * OC_ * OD_;   // 40960, layout [b][o][d]

// route (softmax passes)
constexpr int IBLK = 16;
constexpr int NCHK = 2;
constexpr int BCH  = 64;
constexpr int NT   = 512;             // 8 dpairs x 64 b
constexpr int GX   = IC_ / (IBLK * NCHK);  // 36
constexpr int GY   = B_ / BCH;             // 4
constexpr int W_TILE_F = IBLK * OC_ * OD_ * ID_;  // 20480 floats
constexpr int XI = 65;
constexpr int XH = 1040;
constexpr int X_TILE_F4 = 2 * XH;                 // 2080 float4
constexpr int VS_OFF_F = W_TILE_F + X_TILE_F4 * 4;  // 28800 floats
constexpr int SMEMB_R = (VS_OFF_F + 10240) * 4;     // 156160 B
constexpr int WT_ELEMS = IC_ * OC_ * OD_ * ID_;     // 1474560

// gemm0 (pass 0)
constexpr int NT0 = 512;
constexpr int KB0 = 128;       // kk (=i*8+k) per CTA
constexpr int BT0 = 128;       // b per CTA
constexpr int AST = 130;       // A float4 row stride (128 + pad)
constexpr int A_F4 = 32 * AST; // 4160 float4
constexpr int B_FL = KB0 * 192;                     // 24576 floats
constexpr int SMEMB_G = A_F4 * 16 + B_FL * 4;       // 164864 B
}

typedef unsigned long long ull;

__device__ __align__(16) float g_Wt[WT_ELEMS];      // [i][o][dp][k][dl]
__device__ __align__(16) float g_Wg[9216 * 192];    // [ik][ods*12+c] padded
__device__ __align__(16) float g_s[3][SOD];         // [b][o][d]
__device__ __align__(16) float g_Vsum[SOD];

__device__ __forceinline__ float fast_rcp(float x) {
    float y; asm("rcp.approx.ftz.f32 %0, %1;" : "=f"(y) : "f"(x)); return y;
}
__device__ __forceinline__ float fast_rsqrt(float x) {
    float y; asm("rsqrt.approx.ftz.f32 %0, %1;" : "=f"(y) : "f"(x)); return y;
}
__device__ __forceinline__ ull pack2(float lo, float hi) {
    ull r; asm("mov.b64 %0, {%1, %2};" : "=l"(r) : "f"(lo), "f"(hi)); return r;
}
__device__ __forceinline__ void unpack2(ull v, float& lo, float& hi) {
    asm("mov.b64 {%0, %1}, %2;" : "=f"(lo), "=f"(hi) : "l"(v));
}
__device__ __forceinline__ ull fma2(ull a, ull b, ull c) {
    ull d; asm("fma.rn.f32x2 %0, %1, %2, %3;" : "=l"(d) : "l"(a), "l"(b), "l"(c)); return d;
}
__device__ __forceinline__ ull mul2(ull a, ull b) {
    ull d; asm("mul.rn.f32x2 %0, %1, %2;" : "=l"(d) : "l"(a), "l"(b)); return d;
}
__device__ __forceinline__ ull add2(ull a, ull b) {
    ull d; asm("add.rn.f32x2 %0, %1, %2;" : "=l"(d) : "l"(a), "l"(b)); return d;
}

// Build g_Wt [i][o][dp][k][dl], g_Wg [ik][od padded 10->12], zero accumulators.
__global__ void prepack_zero_kernel(const float* __restrict__ W) {
    int e = blockIdx.x * 512 + threadIdx.x;
    if (e < SOD) {
        g_s[0][e] = 0.f; g_s[1][e] = 0.f; g_s[2][e] = 0.f;
        g_Vsum[e] = 0.f;
    }
    if (e < WT_ELEMS) {
        {   // g_Wt
            int io = e >> 7, r = e & 127;
            int dp = r >> 4, k = (r >> 1) & 7, dl = r & 1;
            g_Wt[e] = W[(io * OD_ + 2 * dp + dl) * ID_ + k];
        }
        {   // g_Wg: row kk = i*8+k, col od = o*16+d at (od/10)*12 + od%10
            int kk = e / 160, od = e - kk * 160;
            int i = kk >> 3, k = kk & 7;
            int o = od >> 4, d = od & 15;
            g_Wg[kk * 192 + (od / 10) * 12 + (od % 10)] =
                W[(((i * OC_) + o) * OD_ + d) * ID_ + k];
        }
    }
}

// Pass-0 GEMM: grid (72, 2), 512 thr = 16 ods-sections x 32 b-lanes.
// Thread: 4 batches (bq + j*32) x 10 od-cols (ods*10..+9) = 20 f32x2 accums.
__global__ __launch_bounds__(NT0) void gemm0_kernel(const float* __restrict__ x) {
    extern __shared__ float sg[];
    float4* A4 = reinterpret_cast<float4*>(sg);     // [h*16+i][AST] float4
    float*  Bf = sg + A_F4 * 4;                     // [kk][192]

    const int t   = threadIdx.x;
    const int ods = t >> 5;      // 0..15 (constant per warp -> B broadcast)
    const int bq  = t & 31;      // lane
    const int b0  = blockIdx.y * BT0;
    const int i0  = blockIdx.x * 16;

    // fill A (coalesced: 32 lanes cover one b-row's 512B)
    {
        const float4* xs = reinterpret_cast<const float4*>(x);
#pragma unroll
        for (int r = 0; r < 8; r++) {
            int f = t + r * NT0;          // 0..4095
            int b = f >> 5, cc = f & 31;
            int i = cc >> 1, h = cc & 1;
            A4[(h * 16 + i) * AST + b] = xs[((size_t)(b0 + b) * IC_ + i0 + i) * 2 + h];
        }
    }
    // fill B (straight copy of padded g_Wg rows)
    {
        const float4* wg = reinterpret_cast<const float4*>(g_Wg)
                           + (size_t)blockIdx.x * KB0 * 48;
        float4* Bd = reinterpret_cast<float4*>(Bf);
#pragma unroll
        for (int r = 0; r < 12; r++)
            Bd[t + r * NT0] = wg[t + r * NT0];
    }
    __syncthreads();

    ull acc[4][5];
    const ull zz = pack2(0.f, 0.f);
#pragma unroll
    for (int j = 0; j < 4; j++)
#pragma unroll
        for (int c = 0; c < 5; c++) acc[j][c] = zz;

    const ulonglong2* B2 = reinterpret_cast<const ulonglong2*>(Bf);
    const ull* Bu = reinterpret_cast<const ull*>(Bf);

    for (int i = 0; i < 16; i++) {
        float4 a[2][4];
#pragma unroll
        for (int h = 0; h < 2; h++)
#pragma unroll
            for (int j = 0; j < 4; j++)
                a[h][j] = A4[(h * 16 + i) * AST + j * 32 + bq];   // conflict-free
#pragma unroll
        for (int k = 0; k < 8; k++) {
            const int h = k >> 2, sel = k & 3;
            ull xp[4];
#pragma unroll
            for (int j = 0; j < 4; j++) {
                float v = (sel == 0) ? a[h][j].x : (sel == 1) ? a[h][j].y
                        : (sel == 2) ? a[h][j].z : a[h][j].w;
                xp[j] = pack2(v, v);
            }
            int rb = (i * 8 + k) * 48 + ods * 3;      // float4 index
            ulonglong2 w01 = B2[rb];                  // broadcast
            ulonglong2 w23 = B2[rb + 1];
            ull w4 = Bu[(i * 8 + k) * 96 + ods * 6 + 4];
#pragma unroll
            for (int j = 0; j < 4; j++) {
                acc[j][0] = fma2(w01.x, xp[j], acc[j][0]);
                acc[j][1] = fma2(w01.y, xp[j], acc[j][1]);
                acc[j][2] = fma2(w23.x, xp[j], acc[j][2]);
                acc[j][3] = fma2(w23.y, xp[j], acc[j][3]);
                acc[j][4] = fma2(w4,    xp[j], acc[j][4]);
            }
        }
    }

    // split-K partials -> g_s[0], scaled by 1/OC (uniform softmax)
#pragma unroll
    for (int j = 0; j < 4; j++) {
        float* sp = g_s[0] + (size_t)(b0 + j * 32 + bq) * 160 + ods * 10;
#pragma unroll
        for (int c = 0; c < 5; c++) {
            float lo, hi; unpack2(acc[j][c], lo, hi);
            atomicAdd(sp + 2 * c,     lo * 0.1f);
            atomicAdd(sp + 2 * c + 1, hi * 0.1f);
        }
    }
}

// Softmax routing pass (t = 1, 2). Grid (36, 4), block 512 = 8 dpair x 64 b.
// Warp = fixed dpair, 32 batches -> every W smem read is a broadcast.
// Vsum staged in smem [o][dp][b] (frees 20 regs for o-chain ILP).
__global__ __launch_bounds__(NT) void route_soft_kernel(
    const float* __restrict__ x,   // [B, IC, ID]
    int which)
{
    extern __shared__ float sm[];
    float* Wsm = sm;                                        // 80 KB
    float4* X4 = reinterpret_cast<float4*>(sm + W_TILE_F);  // [h][i(pad)][b]
    ull* Vs = reinterpret_cast<ull*>(sm + VS_OFF_F);        // [o][dp][b]

    const int t   = threadIdx.x;
    const int dp  = t >> 6;         // 0..7
    const int bl  = t & 63;         // 0..63 (warp: 32 consecutive bl, same dp)
    const int b0  = blockIdx.y * BCH;
    const int b   = b0 + bl;

    // stage this CTA's Vsum slice (each thread its own 10 pairs)
#pragma unroll
    for (int o = 0; o < OC_; o++)
        Vs[(o * 8 + dp) * 64 + bl] = *reinterpret_cast<const ull*>(
            g_Vsum + (((size_t)b * OC_ + o) * OD_ + 2 * dp));

    ull s[OC_];
    const ull zz  = pack2(0.f, 0.f);
    const ull ONE = pack2(1.f, 1.f);
    const ull C12 = pack2(0.5f, 0.5f);
    const ull C16 = pack2(1.f / 6.f, 1.f / 6.f);
#pragma unroll
    for (int o = 0; o < OC_; o++) s[o] = zz;

    for (int c = 0; c < NCHK; c++) {
        const int i0 = blockIdx.x * (IBLK * NCHK) + c * IBLK;
        if (c) __syncthreads();     // drain readers of previous tiles

        // ---- W tile ----
        {
            const float4* src = reinterpret_cast<const float4*>(
                g_Wt + (size_t)i0 * (OC_ * OD_ * ID_));
            float4* dst = reinterpret_cast<float4*>(Wsm);
#pragma unroll
            for (int r = 0; r < W_TILE_F / 4 / NT; r++)   // 10
                dst[t + r * NT] = src[t + r * NT];
        }
        // ---- x tile: [h][i][b] float4, padded strides ----
        {
#pragma unroll
            for (int r = 0; r < 4; r++) {
                int f = t + r * NT;                       // 0..2047
                int bb = f >> 5;                          // 0..63
                int cc = f & 31;
                const float4* src = reinterpret_cast<const float4*>(
                    x + ((size_t)(b0 + bb) * IC_ + i0) * ID_);
                int i = cc >> 1, h = cc & 1;
                X4[h * XH + i * XI + bb] = src[cc];
            }
        }
        __syncthreads();

        const ulonglong2* W2 = reinterpret_cast<const ulonglong2*>(Wsm);

#pragma unroll 4
        for (int i = 0; i < IBLK; i++) {
            float4 xa = X4[i * XI + bl];
            float4 xb = X4[XH + i * XI + bl];
            ull xp[ID_];
            xp[0] = pack2(xa.x, xa.x); xp[1] = pack2(xa.y, xa.y);
            xp[2] = pack2(xa.z, xa.z); xp[3] = pack2(xa.w, xa.w);
            xp[4] = pack2(xb.x, xb.x); xp[5] = pack2(xb.y, xb.y);
            xp[6] = pack2(xb.z, xb.z); xp[7] = pack2(xb.w, xb.w);

            ull u[OC_];
#pragma unroll
            for (int o = 0; o < OC_; o++) {
                int wb = ((i * OC_ + o) * ID_ + dp) * 4;
                ulonglong2 w01 = W2[wb];
                ulonglong2 w23 = W2[wb + 1];
                ulonglong2 w45 = W2[wb + 2];
                ulonglong2 w67 = W2[wb + 3];
                ull acc = mul2(w01.x, xp[0]);
                acc = fma2(w01.y, xp[1], acc);
                acc = fma2(w23.x, xp[2], acc);
                acc = fma2(w23.y, xp[3], acc);
                acc = fma2(w45.x, xp[4], acc);
                acc = fma2(w45.y, xp[5], acc);
                acc = fma2(w67.x, xp[6], acc);
                acc = fma2(w67.y, xp[7], acc);
                u[o] = acc;
            }

            ull Za = zz, Zb = zz;   // split Z tree for ILP
#pragma unroll
            for (int o = 0; o < OC_; o++) {
                // z = u*Vsum is tiny (|z| < ~0.15): cubic Taylor exp.
                ull vp = Vs[(o * 8 + dp) * 64 + bl];
                ull z = mul2(u[o], vp);
                ull p = fma2(z, C16, C12);
                p = fma2(z, p, ONE);
                ull e = fma2(z, p, ONE);
                if (o & 1) Zb = add2(Zb, e); else Za = add2(Za, e);
                u[o] = mul2(u[o], e);         // u now holds u*e
            }
            ull Z2 = add2(Za, Zb);
            float Z0, Z1; unpack2(Z2, Z0, Z1);
            ull rp = pack2(fast_rcp(Z0), fast_rcp(Z1));
#pragma unroll
            for (int o = 0; o < OC_; o++) s[o] = fma2(u[o], rp, s[o]);
        }
    }

    // accumulate partial s into global [b][o][d]
    float* sp = g_s[which] + ((size_t)b * OC_) * OD_ + 2 * dp;
#pragma unroll
    for (int o = 0; o < OC_; o++) {
        float a0, a1; unpack2(s[o], a0, a1);
        atomicAdd(sp + o * OD_, a0);
        atomicAdd(sp + o * OD_ + 1, a1);
    }
}

// squash(s) per (b,o) over d; update Vsum, or write final output.
__global__ void squash_kernel(int which, float* __restrict__ out, int final_) {
    const float* __restrict__ s = g_s[which];
    int t  = blockIdx.x * 256 + threadIdx.x;   // SOD threads exactly
    int d  = t & 15;
    int bo = t >> 4;
    int idx = bo * OD_ + d;                    // [b][o][d]

    float sv = s[idx];
    float l2 = sv * sv;
#pragma unroll
    for (int off = 8; off > 0; off >>= 1)
        l2 += __shfl_xor_sync(0xffffffffu, l2, off);

    float coef = l2 * fast_rsqrt(l2) * fast_rcp(1.f + l2);
    float v = sv * coef;

    if (final_) {
        out[idx] = v;                           // output [B, OC, OD]
    } else {
        g_Vsum[idx] = g_Vsum[idx] + v;
    }
}

extern "C" void kernel_launch(void* const* d_in, const int* in_sizes, int n_in,
                              void* d_out, int out_size) {
    const float* x = (const float*)d_in[0];   // [256,1152,8]
    const float* W = (const float*)d_in[1];   // [1152,10,16,8]
    float* out = (float*)d_out;               // [256,10,16]

    cudaFuncSetAttribute(route_soft_kernel,
                         cudaFuncAttributeMaxDynamicSharedMemorySize, SMEMB_R);
    cudaFuncSetAttribute(gemm0_kernel,
                         cudaFuncAttributeMaxDynamicSharedMemorySize, SMEMB_G);

    dim3 rg(GX, GY);
    int sgrid = SOD / 256;   // 160

    prepack_zero_kernel<<<(WT_ELEMS + 511) / 512, 512>>>(W);

    gemm0_kernel<<<dim3(72, 2), NT0, SMEMB_G>>>(x);
    squash_kernel<<<sgrid, 256>>>(0, out, 0);

    route_soft_kernel<<<rg, NT, SMEMB_R>>>(x, 1);
    squash_kernel<<<sgrid, 256>>>(1, out, 0);

    route_soft_kernel<<<rg, NT, SMEMB_R>>>(x, 2);
    squash_kernel<<<sgrid, 256>>>(2, out, 1);
}

// round 16
// speedup vs baseline: 1.0843x; 1.0843x over previous
#include <cuda_runtime.h>
#include <cstdint>

// CapsNet dynamic routing, fused, f32x2-packed over the OD dimension.
// b_t = u * Vsum so u (189 MB) is never materialized.
// Thread = (batch, d-pair); 32 input-caps in 2 smem chunks, s[o] (f32x2) in
// registers, W pre-transposed so LDS.128 yields packed pairs. Softmax exp =
// cubic Taylor in packed FMA (|z| < ~0.15).
// The inter-pass squash is computed COOPERATIVELY in each route pass's
// prologue (Vs = sum_{tau<PASS} squash(g_s[tau]) into smem), so only the
// final squash remains as its own kernel: 5 launches total.

namespace {
constexpr int B_  = 256;
constexpr int IC_ = 1152;
constexpr int ID_ = 8;
constexpr int OC_ = 10;
constexpr int OD_ = 16;
constexpr int SOD = B_ * OC_ * OD_;   // 40960, layout [b][o][d]

constexpr int IBLK = 16;              // i's per smem chunk
constexpr int NCHK = 2;               // chunks per CTA
constexpr int BCH  = 64;              // batches per CTA
constexpr int NT   = 512;             // 8 dpairs x 64 b
constexpr int GX   = IC_ / (IBLK * NCHK);  // 36
constexpr int GY   = B_ / BCH;             // 4

constexpr int W_TILE_F = IBLK * OC_ * OD_ * ID_;  // 20480 floats (80 KB)
constexpr int XI = 65;                 // float4 stride over i (padded)
constexpr int XH = 1040;               // float4 stride over k-half
constexpr int X_TILE_F4 = 2 * XH;      // 2080 float4
constexpr int VS_OFF_F = W_TILE_F + X_TILE_F4 * 4;  // 28800 floats
constexpr int SMEMB = (VS_OFF_F + 10240) * 4;       // 156160 B
constexpr int WT_ELEMS = IC_ * OC_ * OD_ * ID_;     // 1474560
}

typedef unsigned long long ull;

__device__ __align__(16) float g_Wt[WT_ELEMS];  // [i][o][dp][k][dl]
__device__ __align__(16) float g_s[3][SOD];     // [b][o][d]

__device__ __forceinline__ float fast_rcp(float x) {
    float y; asm("rcp.approx.ftz.f32 %0, %1;" : "=f"(y) : "f"(x)); return y;
}
__device__ __forceinline__ float fast_rsqrt(float x) {
    float y; asm("rsqrt.approx.ftz.f32 %0, %1;" : "=f"(y) : "f"(x)); return y;
}
__device__ __forceinline__ ull pack2(float lo, float hi) {
    ull r; asm("mov.b64 %0, {%1, %2};" : "=l"(r) : "f"(lo), "f"(hi)); return r;
}
__device__ __forceinline__ void unpack2(ull v, float& lo, float& hi) {
    asm("mov.b64 {%0, %1}, %2;" : "=f"(lo), "=f"(hi) : "l"(v));
}
__device__ __forceinline__ ull fma2(ull a, ull b, ull c) {
    ull d; asm("fma.rn.f32x2 %0, %1, %2, %3;" : "=l"(d) : "l"(a), "l"(b), "l"(c)); return d;
}
__device__ __forceinline__ ull mul2(ull a, ull b) {
    ull d; asm("mul.rn.f32x2 %0, %1, %2;" : "=l"(d) : "l"(a), "l"(b)); return d;
}
__device__ __forceinline__ ull add2(ull a, ull b) {
    ull d; asm("add.rn.f32x2 %0, %1, %2;" : "=l"(d) : "l"(a), "l"(b)); return d;
}

// Transpose W[i][o][d][k] -> g_Wt[i][o][dp][k][dl], zero accumulators.
__global__ void prepack_zero_kernel(const float* __restrict__ W) {
    int e = blockIdx.x * 512 + threadIdx.x;
    if (e < SOD) {
        g_s[0][e] = 0.f; g_s[1][e] = 0.f; g_s[2][e] = 0.f;
    }
    if (e < WT_ELEMS) {
        int io = e >> 7;          // 128 floats per (i,o)
        int r  = e & 127;
        int dp = r >> 4;
        int k  = (r >> 1) & 7;
        int dl = r & 1;
        g_Wt[e] = W[(io * OD_ + 2 * dp + dl) * ID_ + k];
    }
}

// Routing pass PASS = 0,1,2. Grid (36, 4), block 512 = 8 dpair x 64 b.
// Warp = fixed dpair, 32 batches -> every W smem read is a broadcast.
// PASS>0: prologue cooperatively builds Vs = sum squash(g_s[tau]) in smem.
template<int PASS>
__global__ __launch_bounds__(NT) void route_kernel(
    const float* __restrict__ x)   // [B, IC, ID]
{
    extern __shared__ float sm[];
    float* Wsm = sm;                                        // 80 KB
    float4* X4 = reinterpret_cast<float4*>(sm + W_TILE_F);  // [h][i(pad)][b]
    ull* Vs = reinterpret_cast<ull*>(sm + VS_OFF_F);        // [o][dp][b]

    const int t   = threadIdx.x;
    const int dp  = t >> 6;         // 0..7
    const int bl  = t & 63;         // 0..63 (warp: 32 consecutive bl, same dp)
    const int b0  = blockIdx.y * BCH;
    const int b   = b0 + bl;

    // ---- prologue: cooperative squash of prior passes into smem Vs ----
    if (PASS > 0) {
        for (int r = t; r < BCH * OC_; r += NT) {           // 640 rows
            int bb = r / OC_;
            int o  = r - bb * OC_;
            size_t gid = (size_t)(b0 + bb) * OC_ + o;
            float v[OD_];
#pragma unroll
            for (int d = 0; d < OD_; d++) v[d] = 0.f;
#pragma unroll
            for (int tau = 0; tau < PASS; tau++) {
                const float4* s4 = reinterpret_cast<const float4*>(
                    g_s[tau] + gid * OD_);
                float4 q0 = s4[0], q1 = s4[1], q2 = s4[2], q3 = s4[3];
                float l2 = q0.x * q0.x;
                l2 = fmaf(q0.y, q0.y, l2); l2 = fmaf(q0.z, q0.z, l2);
                l2 = fmaf(q0.w, q0.w, l2); l2 = fmaf(q1.x, q1.x, l2);
                l2 = fmaf(q1.y, q1.y, l2); l2 = fmaf(q1.z, q1.z, l2);
                l2 = fmaf(q1.w, q1.w, l2); l2 = fmaf(q2.x, q2.x, l2);
                l2 = fmaf(q2.y, q2.y, l2); l2 = fmaf(q2.z, q2.z, l2);
                l2 = fmaf(q2.w, q2.w, l2); l2 = fmaf(q3.x, q3.x, l2);
                l2 = fmaf(q3.y, q3.y, l2); l2 = fmaf(q3.z, q3.z, l2);
                l2 = fmaf(q3.w, q3.w, l2);
                // squash coef = ||s|| / (1 + ||s||^2)
                float cf = l2 * fast_rsqrt(l2) * fast_rcp(1.f + l2);
                v[0]  = fmaf(q0.x, cf, v[0]);  v[1]  = fmaf(q0.y, cf, v[1]);
                v[2]  = fmaf(q0.z, cf, v[2]);  v[3]  = fmaf(q0.w, cf, v[3]);
                v[4]  = fmaf(q1.x, cf, v[4]);  v[5]  = fmaf(q1.y, cf, v[5]);
                v[6]  = fmaf(q1.z, cf, v[6]);  v[7]  = fmaf(q1.w, cf, v[7]);
                v[8]  = fmaf(q2.x, cf, v[8]);  v[9]  = fmaf(q2.y, cf, v[9]);
                v[10] = fmaf(q2.z, cf, v[10]); v[11] = fmaf(q2.w, cf, v[11]);
                v[12] = fmaf(q3.x, cf, v[12]); v[13] = fmaf(q3.y, cf, v[13]);
                v[14] = fmaf(q3.z, cf, v[14]); v[15] = fmaf(q3.w, cf, v[15]);
            }
#pragma unroll
            for (int d2 = 0; d2 < 8; d2++)
                Vs[(o * 8 + d2) * 64 + bb] = pack2(v[2 * d2], v[2 * d2 + 1]);
        }
    }

    ull s[OC_];
    const ull zz  = pack2(0.f, 0.f);
    const ull ONE = pack2(1.f, 1.f);
    const ull C12 = pack2(0.5f, 0.5f);
    const ull C16 = pack2(1.f / 6.f, 1.f / 6.f);
#pragma unroll
    for (int o = 0; o < OC_; o++) s[o] = zz;

    for (int c = 0; c < NCHK; c++) {
        const int i0 = blockIdx.x * (IBLK * NCHK) + c * IBLK;
        if (c) __syncthreads();     // drain readers of previous tiles

        // ---- W tile: straight copy of pre-transposed weights ----
        {
            const float4* src = reinterpret_cast<const float4*>(
                g_Wt + (size_t)i0 * (OC_ * OD_ * ID_));
            float4* dst = reinterpret_cast<float4*>(Wsm);
#pragma unroll
            for (int r = 0; r < W_TILE_F / 4 / NT; r++)   // 10
                dst[t + r * NT] = src[t + r * NT];
        }
        // ---- x tile: [h][i][b] float4, padded strides ----
        {
#pragma unroll
            for (int r = 0; r < 4; r++) {
                int f = t + r * NT;                       // 0..2047
                int bb = f >> 5;                          // 0..63
                int cc = f & 31;
                const float4* src = reinterpret_cast<const float4*>(
                    x + ((size_t)(b0 + bb) * IC_ + i0) * ID_);
                int i = cc >> 1, h = cc & 1;
                X4[h * XH + i * XI + bb] = src[cc];
            }
        }
        __syncthreads();   // also publishes prologue's Vs on c==0

        const ulonglong2* W2 = reinterpret_cast<const ulonglong2*>(Wsm);

#pragma unroll 4
        for (int i = 0; i < IBLK; i++) {
            float4 xa = X4[i * XI + bl];
            float4 xb = X4[XH + i * XI + bl];
            ull xp[ID_];
            xp[0] = pack2(xa.x, xa.x); xp[1] = pack2(xa.y, xa.y);
            xp[2] = pack2(xa.z, xa.z); xp[3] = pack2(xa.w, xa.w);
            xp[4] = pack2(xb.x, xb.x); xp[5] = pack2(xb.y, xb.y);
            xp[6] = pack2(xb.z, xb.z); xp[7] = pack2(xb.w, xb.w);

            ull u[OC_];
#pragma unroll
            for (int o = 0; o < OC_; o++) {
                // broadcast LDS.128: two packed W pairs each
                int wb = ((i * OC_ + o) * ID_ + dp) * 4;
                ulonglong2 w01 = W2[wb];
                ulonglong2 w23 = W2[wb + 1];
                ulonglong2 w45 = W2[wb + 2];
                ulonglong2 w67 = W2[wb + 3];
                ull acc = mul2(w01.x, xp[0]);
                acc = fma2(w01.y, xp[1], acc);
                acc = fma2(w23.x, xp[2], acc);
                acc = fma2(w23.y, xp[3], acc);
                acc = fma2(w45.x, xp[4], acc);
                acc = fma2(w45.y, xp[5], acc);
                acc = fma2(w67.x, xp[6], acc);
                acc = fma2(w67.y, xp[7], acc);
                u[o] = acc;
            }

            if (PASS == 0) {
#pragma unroll
                for (int o = 0; o < OC_; o++) s[o] = add2(s[o], u[o]);
            } else {
                ull Za = zz, Zb = zz;   // split Z tree for ILP
#pragma unroll
                for (int o = 0; o < OC_; o++) {
                    // z = u*Vsum is tiny (|z| < ~0.15): cubic Taylor exp,
                    // all on the FMA pipe, fully packed.
                    ull vp = Vs[(o * 8 + dp) * 64 + bl];
                    ull z = mul2(u[o], vp);
                    ull p = fma2(z, C16, C12);
                    p = fma2(z, p, ONE);
                    ull e = fma2(z, p, ONE);
                    if (o & 1) Zb = add2(Zb, e); else Za = add2(Za, e);
                    u[o] = mul2(u[o], e);         // u now holds u*e
                }
                ull Z2 = add2(Za, Zb);
                float Z0, Z1; unpack2(Z2, Z0, Z1);
                ull rp = pack2(fast_rcp(Z0), fast_rcp(Z1));
#pragma unroll
                for (int o = 0; o < OC_; o++) s[o] = fma2(u[o], rp, s[o]);
            }
        }
    }

    // accumulate partial s into global [b][o][d]
    float* sp = g_s[PASS] + ((size_t)b * OC_) * OD_ + 2 * dp;
#pragma unroll
    for (int o = 0; o < OC_; o++) {
        float a0, a1; unpack2(s[o], a0, a1);
        if (PASS == 0) { a0 *= (1.0f / OC_); a1 *= (1.0f / OC_); }
        atomicAdd(sp + o * OD_, a0);
        atomicAdd(sp + o * OD_ + 1, a1);
    }
}

// Final squash: out = squash(g_s[2]) per (b,o) over d.
__global__ void squash_final_kernel(float* __restrict__ out) {
    const float* __restrict__ s = g_s[2];
    int t  = blockIdx.x * 256 + threadIdx.x;   // SOD threads exactly
    int d  = t & 15;
    int bo = t >> 4;
    int idx = bo * OD_ + d;                    // [b][o][d]

    float sv = s[idx];
    float l2 = sv * sv;
#pragma unroll
    for (int off = 8; off > 0; off >>= 1)
        l2 += __shfl_xor_sync(0xffffffffu, l2, off);

    float coef = l2 * fast_rsqrt(l2) * fast_rcp(1.f + l2);
    out[idx] = sv * coef;                      // output [B, OC, OD]
}

extern "C" void kernel_launch(void* const* d_in, const int* in_sizes, int n_in,
                              void* d_out, int out_size) {
    const float* x = (const float*)d_in[0];   // [256,1152,8]
    const float* W = (const float*)d_in[1];   // [1152,10,16,8]
    float* out = (float*)d_out;               // [256,10,16]

    cudaFuncSetAttribute(route_kernel<0>,
                         cudaFuncAttributeMaxDynamicSharedMemorySize, SMEMB);
    cudaFuncSetAttribute(route_kernel<1>,
                         cudaFuncAttributeMaxDynamicSharedMemorySize, SMEMB);
    cudaFuncSetAttribute(route_kernel<2>,
                         cudaFuncAttributeMaxDynamicSharedMemorySize, SMEMB);

    dim3 rg(GX, GY);

    prepack_zero_kernel<<<(WT_ELEMS + 511) / 512, 512>>>(W);
    route_kernel<0><<<rg, NT, SMEMB>>>(x);
    route_kernel<1><<<rg, NT, SMEMB>>>(x);
    route_kernel<2><<<rg, NT, SMEMB>>>(x);
    squash_final_kernel<<<SOD / 256, 256>>>(out);
}